// round 6
// baseline (speedup 1.0000x reference)
#include <cuda_runtime.h>
#include <cuda_fp16.h>
#include <cstdint>
#include <math.h>

#define B_  2
#define L_  2048
#define DIM_ 2048
#define H_  16
#define HD_ 128
#define QKV_ 2304   // 2048 q + 128 k + 128 v

// ---------------------------------------------------------------------------
// Scratch (device globals)
// ---------------------------------------------------------------------------
__device__ __half g_xh   [(size_t)B_ * L_ * DIM_];   // x in half
__device__ __half g_wqkvt[(size_t)QKV_ * DIM_];      // [Wq^T;Wk^T;Wv^T] half [2304][2048]
__device__ __half g_wot  [(size_t)DIM_ * DIM_];      // Wo^T half
__device__ __half g_qkv  [(size_t)B_ * L_ * QKV_];   // fused q|k|v proj (roped in place)
__device__ __half g_aoh  [(size_t)B_ * L_ * DIM_];   // attention out half

// ---------------------------------------------------------------------------
// PTX helpers
// ---------------------------------------------------------------------------
__device__ __forceinline__ uint32_t smem_u32(const void* p) {
    uint32_t a;
    asm("{ .reg .u64 t; cvta.to.shared.u64 t, %1; cvt.u32.u64 %0, t; }"
        : "=r"(a) : "l"(p));
    return a;
}
__device__ __forceinline__ void cp16(uint32_t dst, const void* src) {
    asm volatile("cp.async.cg.shared.global [%0], [%1], 16;" :: "r"(dst), "l"(src));
}
#define CP_COMMIT() asm volatile("cp.async.commit_group;")
#define CP_WAIT(n)  asm volatile("cp.async.wait_group %0;" :: "n"(n))

__device__ __forceinline__ void ldsm_x4(uint32_t* r, uint32_t addr) {
    asm volatile("ldmatrix.sync.aligned.m8n8.x4.shared.b16 {%0,%1,%2,%3}, [%4];"
        : "=r"(r[0]), "=r"(r[1]), "=r"(r[2]), "=r"(r[3]) : "r"(addr));
}
__device__ __forceinline__ void ldsm_x4_t(uint32_t* r, uint32_t addr) {
    asm volatile("ldmatrix.sync.aligned.m8n8.x4.trans.shared.b16 {%0,%1,%2,%3}, [%4];"
        : "=r"(r[0]), "=r"(r[1]), "=r"(r[2]), "=r"(r[3]) : "r"(addr));
}
__device__ __forceinline__ void mma16(float* d, const uint32_t* a,
                                      uint32_t b0, uint32_t b1) {
    asm volatile(
        "mma.sync.aligned.m16n8k16.row.col.f32.f16.f16.f32 "
        "{%0,%1,%2,%3}, {%4,%5,%6,%7}, {%8,%9}, {%0,%1,%2,%3};"
        : "+f"(d[0]), "+f"(d[1]), "+f"(d[2]), "+f"(d[3])
        : "r"(a[0]), "r"(a[1]), "r"(a[2]), "r"(a[3]), "r"(b0), "r"(b1));
}
__device__ __forceinline__ uint32_t pkh2(float lo, float hi) {
    uint32_t r;
    asm("cvt.rn.f16x2.f32 %0, %1, %2;" : "=r"(r) : "f"(hi), "f"(lo));
    return r;
}

// ---------------------------------------------------------------------------
// f32 -> half conversion
// ---------------------------------------------------------------------------
__global__ __launch_bounds__(256) void f2h_kernel(
    const float* __restrict__ in, __half* __restrict__ out, int n4)
{
    int i = blockIdx.x * blockDim.x + threadIdx.x;
    if (i < n4) {
        float4 v = ((const float4*)in)[i];
        ((uint2*)out)[i] = make_uint2(pkh2(v.x, v.y), pkh2(v.z, v.w));
    }
}

// ---------------------------------------------------------------------------
// Transpose f32 -> half: out[c][r] = in[r][c], out row stride = ostride
// ---------------------------------------------------------------------------
__global__ __launch_bounds__(256) void transpose_h_kernel(
    const float* __restrict__ in, __half* __restrict__ out,
    int R, int C, int ostride)
{
    __shared__ float t[32][33];
    const int c0 = blockIdx.x * 32, r0 = blockIdx.y * 32;
    const int x = threadIdx.x, y = threadIdx.y;  // 32 x 8
    #pragma unroll
    for (int i = 0; i < 32; i += 8)
        t[y + i][x] = in[(size_t)(r0 + y + i) * C + c0 + x];
    __syncthreads();
    #pragma unroll
    for (int i = 0; i < 32; i += 8)
        out[(size_t)(c0 + y + i) * ostride + r0 + x] = __float2half_rn(t[x][y + i]);
}

// ---------------------------------------------------------------------------
// fp16 mma GEMM: C[M,N] = A[M,K] * Bt[N,K]^T.
// BM=128, BN=256, BK=32, 4-stage cp.async, 256 threads = 8 warps (2m x 4n),
// warp tile 64x64 (1.0 LDS wavefront per mma).
// smem row: 32 halves + pad -> 80B stride.
// ---------------------------------------------------------------------------
#define GA_STG 10240            // 128 rows * 80B
#define GB_STG 20480            // 256 rows * 80B
#define G_STG  (GA_STG + GB_STG)
#define GEMM_SMEM (4 * G_STG)   // 122880

template<bool OUT_HALF>
__global__ __launch_bounds__(256) void gemm16_kernel(
    int M, int N, int K,
    const __half* __restrict__ A, const __half* __restrict__ Bt, void* Cout)
{
    extern __shared__ char smem[];
    const uint32_t sA = smem_u32(smem);            // stage s: sA + s*G_STG
    const uint32_t sB = sA + GA_STG;               // within stage

    const int tid = threadIdx.x, wid = tid >> 5, lane = tid & 31;
    const int grp = lane >> 2, tig = lane & 3;
    const int lrow = lane & 15, lhi = lane >> 4;
    const int wm = wid & 1, wn = wid >> 1;         // 2m x 4n
    const int bm = blockIdx.y * 128, bn = blockIdx.x * 256;

    float acc[4][8][4];
    #pragma unroll
    for (int mt = 0; mt < 4; ++mt)
        #pragma unroll
        for (int nb = 0; nb < 8; ++nb)
            #pragma unroll
            for (int e = 0; e < 4; ++e) acc[mt][nb][e] = 0.f;

    // A loader: 128 rows x 32 halves = 8KB, 2 cp16/thread
    const int a_row = tid >> 1, a_ch = (tid & 1) * 2;
    const __half* Asrc = A + (size_t)(bm + a_row) * K + a_ch * 8;
    const uint32_t Adst = a_row * 80 + a_ch * 16;
    // B loader: 256 rows x 32 halves = 16KB, 4 cp16/thread (1 row/thread)
    const __half* Bsrc = Bt + (size_t)(bn + tid) * K;
    const uint32_t Bdst = tid * 80;

    auto issue = [&](int it, int stg) {
        const __half* as = Asrc + it * 32;
        const __half* bs = Bsrc + it * 32;
        const uint32_t ad = sA + stg * G_STG + Adst;
        const uint32_t bd = sB + stg * G_STG + Bdst;
        cp16(ad, as); cp16(ad + 16, as + 8);
        #pragma unroll
        for (int c = 0; c < 4; ++c) cp16(bd + c * 16, bs + c * 8);
    };

    const int NIT = K / 32;
    issue(0, 0); CP_COMMIT();
    issue(1, 1); CP_COMMIT();
    issue(2, 2); CP_COMMIT();

    const uint32_t offA0 = (wm * 64 + lrow) * 80 + lhi * 16;
    const uint32_t offB0 = (wn * 64 + lrow) * 80 + lhi * 16;

    for (int it = 0; it < NIT; ++it) {
        CP_WAIT(2);
        __syncthreads();
        if (it + 3 < NIT) issue(it + 3, (it + 3) & 3);
        CP_COMMIT();

        const uint32_t cA = sA + (it & 3) * G_STG + offA0;
        const uint32_t cB = sB + (it & 3) * G_STG + offB0;
        #pragma unroll
        for (int ks = 0; ks < 2; ++ks) {
            uint32_t a[4][4];
            #pragma unroll
            for (int mt = 0; mt < 4; ++mt)
                ldsm_x4(a[mt], cA + mt * 16 * 80 + ks * 32);
            #pragma unroll
            for (int j = 0; j < 4; ++j) {
                uint32_t bb[4];
                ldsm_x4(bb, cB + j * 16 * 80 + ks * 32);
                #pragma unroll
                for (int mt = 0; mt < 4; ++mt) {
                    mma16(acc[mt][2 * j],     a[mt], bb[0], bb[2]);
                    mma16(acc[mt][2 * j + 1], a[mt], bb[1], bb[3]);
                }
            }
        }
    }

    #pragma unroll
    for (int mt = 0; mt < 4; ++mt) {
        const int m = bm + wm * 64 + mt * 16 + grp;
        #pragma unroll
        for (int nb = 0; nb < 8; ++nb) {
            const int n = bn + wn * 64 + nb * 8 + 2 * tig;
            if (OUT_HALF) {
                __half* C = (__half*)Cout;
                *(uint32_t*)&C[(size_t)m * N + n] = pkh2(acc[mt][nb][0], acc[mt][nb][1]);
                *(uint32_t*)&C[(size_t)(m + 8) * N + n] = pkh2(acc[mt][nb][2], acc[mt][nb][3]);
            } else {
                float* C = (float*)Cout;
                *(float2*)&C[(size_t)m * N + n] = make_float2(acc[mt][nb][0], acc[mt][nb][1]);
                *(float2*)&C[(size_t)(m + 8) * N + n] = make_float2(acc[mt][nb][2], acc[mt][nb][3]);
            }
        }
    }
}

// ---------------------------------------------------------------------------
// Fused RoPE + RMSNorm, half in/out, in place. One warp per 128-dim vector.
// p = buf + (vec/vpt)*tokstride + (vec%vpt)*128
// ---------------------------------------------------------------------------
__global__ __launch_bounds__(256) void rope16_kernel(
    __half* __restrict__ buf, int tokstride, int vpt,
    const float* __restrict__ cosb, const float* __restrict__ sinb)
{
    const int vec = (blockIdx.x * blockDim.x + threadIdx.x) >> 5;
    const int lane = threadIdx.x & 31;
    const int tok = vec / vpt;
    const int l = tok % L_;

    __half* p = buf + (size_t)tok * tokstride + (size_t)(vec % vpt) * 128;
    float e0 = __half2float(p[lane]);
    float e1 = __half2float(p[lane + 32]);
    float e2 = __half2float(p[lane + 64]);
    float e3 = __half2float(p[lane + 96]);
    float c0 = cosb[l * 64 + lane];
    float s0 = sinb[l * 64 + lane];
    float c1 = cosb[l * 64 + lane + 32];
    float s1 = sinb[l * 64 + lane + 32];

    float r0 =  e0 * c0 + e2 * s0;
    float r2 = -e0 * s0 + e2 * c0;
    float r1 =  e1 * c1 + e3 * s1;
    float r3 = -e1 * s1 + e3 * c1;

    float ss = r0 * r0 + r1 * r1 + r2 * r2 + r3 * r3;
    #pragma unroll
    for (int o = 16; o; o >>= 1) ss += __shfl_xor_sync(0xffffffffu, ss, o);
    float sc = rsqrtf(ss * (1.0f / 128.0f) + 1e-6f);

    p[lane]      = __float2half_rn(r0 * sc);
    p[lane + 32] = __float2half_rn(r1 * sc);
    p[lane + 64] = __float2half_rn(r2 * sc);
    p[lane + 96] = __float2half_rn(r3 * sc);
}

// ---------------------------------------------------------------------------
// fp16 flash attention (causal MQA) reading fused qkv buffer (stride 2304).
// BQ=128 rows/CTA, key tiles of 64, 8 warps each owning a 16-row band.
// ---------------------------------------------------------------------------
#define FL_SMEM (128*272 + 4*64*272)    // Q + 2*(K+V)

__global__ __launch_bounds__(256) void flash16_kernel(
    const __half* __restrict__ qkv, __half* __restrict__ aoh)
{
    extern __shared__ char smem[];
    const uint32_t sQ = smem_u32(smem);
    const uint32_t sKV = sQ + 128 * 272;   // [2 bufs][K 64 rows | V 64 rows]

    const int tid = threadIdx.x, w = tid >> 5, lane = tid & 31;
    const int grp = lane >> 2, tig = lane & 3;
    const int lrow = lane & 15, lhi = lane >> 4;
    const int qx = gridDim.x - 1 - blockIdx.x;     // heavy blocks first
    const int q0 = qx * 128, h = blockIdx.y, b = blockIdx.z;

    // Q tile 128x128 (cols h*128 .. h*128+127 of qkv)
    {
        const int row = tid >> 1, c0 = (tid & 1) * 8;
        const __half* src = qkv + (size_t)(b * L_ + q0 + row) * QKV_ + h * HD_ + c0 * 8;
        const uint32_t dst = sQ + row * 272 + c0 * 16;
        #pragma unroll
        for (int c = 0; c < 8; ++c) cp16(dst + c * 16, src + c * 8);
    }
    const int kvrow = tid >> 2, kvc = (tid & 3) * 4;
    auto issue_kv = [&](int k0, int buf) {
        const __half* base = qkv + (size_t)(b * L_ + k0 + kvrow) * QKV_ + 2048 + kvc * 8;
        const uint32_t kd = sKV + buf * (2 * 64 * 272) + kvrow * 272 + kvc * 16;
        const uint32_t vd = kd + 64 * 272;
        #pragma unroll
        for (int c = 0; c < 4; ++c) {
            cp16(kd + c * 16, base + c * 8);          // k: qkv cols 2048..2175
            cp16(vd + c * 16, base + 128 + c * 8);    // v: qkv cols 2176..2303
        }
    };
    issue_kv(0, 0); CP_COMMIT(); CP_WAIT(0); __syncthreads();

    float m0 = -1e30f, m1 = -1e30f, l0 = 0.f, l1 = 0.f;
    float o[16][4];
    #pragma unroll
    for (int d = 0; d < 16; ++d)
        #pragma unroll
        for (int e = 0; e < 4; ++e) o[d][e] = 0.f;

    const float sc = 0.08838834764831843f * 1.4426950408889634f;  // scale*log2e
    const int ntiles = q0 / 64 + 2;
    const int wrow = q0 + w * 16;

    for (int t = 0; t < ntiles; ++t) {
        const int k0 = t * 64;
        if (t + 1 < ntiles) { issue_kv(k0 + 64, (t + 1) & 1); CP_COMMIT(); }

        const uint32_t cK = sKV + (t & 1) * (2 * 64 * 272);
        const uint32_t cV = cK + 64 * 272;

        if (k0 <= wrow + 15) {
            float s[8][4];
            #pragma unroll
            for (int nb = 0; nb < 8; ++nb)
                #pragma unroll
                for (int e = 0; e < 4; ++e) s[nb][e] = 0.f;

            #pragma unroll
            for (int ks = 0; ks < 8; ++ks) {
                uint32_t a[4];
                ldsm_x4(a, sQ + (w * 16 + lrow) * 272 + (2 * ks + lhi) * 16);
                #pragma unroll
                for (int j = 0; j < 4; ++j) {
                    uint32_t bb[4];
                    ldsm_x4(bb, cK + (j * 16 + lrow) * 272 + (2 * ks + lhi) * 16);
                    mma16(s[2 * j],     a, bb[0], bb[2]);
                    mma16(s[2 * j + 1], a, bb[1], bb[3]);
                }
            }
            #pragma unroll
            for (int nb = 0; nb < 8; ++nb)
                #pragma unroll
                for (int e = 0; e < 4; ++e) s[nb][e] *= sc;
            if (k0 + 63 > wrow) {          // diagonal tile: mask
                const int r0g = wrow + grp, r1g = r0g + 8;
                #pragma unroll
                for (int nb = 0; nb < 8; ++nb) {
                    const int cg = k0 + nb * 8 + 2 * tig;
                    if (cg     > r0g) s[nb][0] = -1e30f;
                    if (cg + 1 > r0g) s[nb][1] = -1e30f;
                    if (cg     > r1g) s[nb][2] = -1e30f;
                    if (cg + 1 > r1g) s[nb][3] = -1e30f;
                }
            }
            float mx0 = -1e30f, mx1 = -1e30f;
            #pragma unroll
            for (int nb = 0; nb < 8; ++nb) {
                mx0 = fmaxf(mx0, fmaxf(s[nb][0], s[nb][1]));
                mx1 = fmaxf(mx1, fmaxf(s[nb][2], s[nb][3]));
            }
            mx0 = fmaxf(mx0, __shfl_xor_sync(0xffffffffu, mx0, 1));
            mx0 = fmaxf(mx0, __shfl_xor_sync(0xffffffffu, mx0, 2));
            mx1 = fmaxf(mx1, __shfl_xor_sync(0xffffffffu, mx1, 1));
            mx1 = fmaxf(mx1, __shfl_xor_sync(0xffffffffu, mx1, 2));
            const float mn0 = fmaxf(m0, mx0), mn1 = fmaxf(m1, mx1);
            const float al0 = exp2f(m0 - mn0), al1 = exp2f(m1 - mn1);
            m0 = mn0; m1 = mn1;

            float sum0 = 0.f, sum1 = 0.f;
            #pragma unroll
            for (int nb = 0; nb < 8; ++nb) {
                s[nb][0] = exp2f(s[nb][0] - mn0); sum0 += s[nb][0];
                s[nb][1] = exp2f(s[nb][1] - mn0); sum0 += s[nb][1];
                s[nb][2] = exp2f(s[nb][2] - mn1); sum1 += s[nb][2];
                s[nb][3] = exp2f(s[nb][3] - mn1); sum1 += s[nb][3];
            }
            sum0 += __shfl_xor_sync(0xffffffffu, sum0, 1);
            sum0 += __shfl_xor_sync(0xffffffffu, sum0, 2);
            sum1 += __shfl_xor_sync(0xffffffffu, sum1, 1);
            sum1 += __shfl_xor_sync(0xffffffffu, sum1, 2);
            l0 = l0 * al0 + sum0;
            l1 = l1 * al1 + sum1;

            uint32_t pa[4][4];
            #pragma unroll
            for (int kp = 0; kp < 4; ++kp) {
                pa[kp][0] = pkh2(s[2 * kp][0],     s[2 * kp][1]);
                pa[kp][1] = pkh2(s[2 * kp][2],     s[2 * kp][3]);
                pa[kp][2] = pkh2(s[2 * kp + 1][0], s[2 * kp + 1][1]);
                pa[kp][3] = pkh2(s[2 * kp + 1][2], s[2 * kp + 1][3]);
            }
            #pragma unroll
            for (int d = 0; d < 16; ++d) {
                o[d][0] *= al0; o[d][1] *= al0;
                o[d][2] *= al1; o[d][3] *= al1;
            }
            #pragma unroll
            for (int kp = 0; kp < 4; ++kp)
                #pragma unroll
                for (int j = 0; j < 8; ++j) {
                    uint32_t vv[4];
                    ldsm_x4_t(vv, cV + (kp * 16 + lrow) * 272 + (2 * j + lhi) * 16);
                    mma16(o[2 * j],     pa[kp], vv[0], vv[1]);
                    mma16(o[2 * j + 1], pa[kp], vv[2], vv[3]);
                }
        }
        if (t + 1 < ntiles) { CP_WAIT(0); __syncthreads(); }
    }

    const float inv0 = 1.f / l0, inv1 = 1.f / l1;
    const int r0g = q0 + w * 16 + grp;
    __half* op0 = aoh + (size_t)(b * L_ + r0g) * DIM_ + h * HD_;
    __half* op1 = op0 + (size_t)8 * DIM_;
    #pragma unroll
    for (int d = 0; d < 16; ++d) {
        const int col = d * 8 + 2 * tig;
        *(uint32_t*)(op0 + col) = pkh2(o[d][0] * inv0, o[d][1] * inv0);
        *(uint32_t*)(op1 + col) = pkh2(o[d][2] * inv1, o[d][3] * inv1);
    }
}

// ---------------------------------------------------------------------------
extern "C" void kernel_launch(void* const* d_in, const int* in_sizes, int n_in,
                              void* d_out, int out_size)
{
    const float* x    = (const float*)d_in[0];
    const float* cosb = (const float*)d_in[1];
    const float* sinb = (const float*)d_in[2];
    const float* Wq   = (const float*)d_in[3];
    const float* Wk   = (const float*)d_in[4];
    const float* Wv   = (const float*)d_in[5];
    const float* Wo   = (const float*)d_in[6];
    float* out = (float*)d_out;

    __half *xh, *wqkvt, *wot, *qkv, *aoh;
    cudaGetSymbolAddress((void**)&xh,    g_xh);
    cudaGetSymbolAddress((void**)&wqkvt, g_wqkvt);
    cudaGetSymbolAddress((void**)&wot,   g_wot);
    cudaGetSymbolAddress((void**)&qkv,   g_qkv);
    cudaGetSymbolAddress((void**)&aoh,   g_aoh);

    const int M = B_ * L_;   // 4096

    cudaFuncSetAttribute(gemm16_kernel<true>,
                         cudaFuncAttributeMaxDynamicSharedMemorySize, GEMM_SMEM);
    cudaFuncSetAttribute(gemm16_kernel<false>,
                         cudaFuncAttributeMaxDynamicSharedMemorySize, GEMM_SMEM);
    cudaFuncSetAttribute(flash16_kernel,
                         cudaFuncAttributeMaxDynamicSharedMemorySize, FL_SMEM);

    // 0) convert x to half; transpose weights to half [N][K], QKV fused
    f2h_kernel<<<(M * DIM_ / 4 + 255) / 256, 256>>>(x, xh, M * DIM_ / 4);
    transpose_h_kernel<<<dim3(DIM_/32, DIM_/32), dim3(32,8)>>>(Wq, wqkvt, DIM_, DIM_, DIM_);
    transpose_h_kernel<<<dim3(HD_/32,  DIM_/32), dim3(32,8)>>>(Wk, wqkvt + (size_t)2048 * DIM_, DIM_, HD_, DIM_);
    transpose_h_kernel<<<dim3(HD_/32,  DIM_/32), dim3(32,8)>>>(Wv, wqkvt + (size_t)2176 * DIM_, DIM_, HD_, DIM_);
    transpose_h_kernel<<<dim3(DIM_/32, DIM_/32), dim3(32,8)>>>(Wo, wot, DIM_, DIM_, DIM_);

    // 1) fused QKV projection: (4096, 2304) = xh @ wqkvt^T
    gemm16_kernel<true><<<dim3(QKV_/256, M/128), 256, GEMM_SMEM>>>(M, QKV_, DIM_, xh, wqkvt, qkv);

    // 2) RoPE + RMSNorm in place (q: 65536 vecs; k: 4096 vecs at col 2048)
    rope16_kernel<<<M * H_ / 8, 256>>>(qkv, QKV_, 16, cosb, sinb);
    rope16_kernel<<<M / 8, 256>>>(qkv + 2048, QKV_, 1, cosb, sinb);

    // 3) fp16 flash attention
    flash16_kernel<<<dim3(L_/128, H_, B_), 256, FL_SMEM>>>(qkv, aoh);

    // 4) output projection (float out)
    gemm16_kernel<false><<<dim3(DIM_/256, M/128), 256, GEMM_SMEM>>>(M, DIM_, DIM_, aoh, wot, out);
}

// round 7
// speedup vs baseline: 1.1199x; 1.1199x over previous
#include <cuda_runtime.h>
#include <cuda_fp16.h>
#include <cstdint>
#include <math.h>

#define B_  2
#define L_  2048
#define DIM_ 2048
#define H_  16
#define HD_ 128
#define QKV_ 2304   // 2048 q + 128 k + 128 v

// ---------------------------------------------------------------------------
// Scratch (device globals)
// ---------------------------------------------------------------------------
__device__ __half g_xh   [(size_t)B_ * L_ * DIM_];   // x in half
__device__ __half g_wqkvt[(size_t)QKV_ * DIM_];      // [Wq^T;Wk^T;Wv^T] half [2304][2048]
__device__ __half g_wot  [(size_t)DIM_ * DIM_];      // Wo^T half
__device__ __half g_qkv  [(size_t)B_ * L_ * QKV_];   // fused q|k|v proj (roped in place)
__device__ __half g_aoh  [(size_t)B_ * L_ * DIM_];   // attention out half

// ---------------------------------------------------------------------------
// PTX helpers
// ---------------------------------------------------------------------------
__device__ __forceinline__ uint32_t smem_u32(const void* p) {
    uint32_t a;
    asm("{ .reg .u64 t; cvta.to.shared.u64 t, %1; cvt.u32.u64 %0, t; }"
        : "=r"(a) : "l"(p));
    return a;
}
__device__ __forceinline__ void cp16(uint32_t dst, const void* src) {
    asm volatile("cp.async.cg.shared.global [%0], [%1], 16;" :: "r"(dst), "l"(src));
}
#define CP_COMMIT() asm volatile("cp.async.commit_group;")
#define CP_WAIT(n)  asm volatile("cp.async.wait_group %0;" :: "n"(n))

__device__ __forceinline__ void ldsm_x4(uint32_t* r, uint32_t addr) {
    asm volatile("ldmatrix.sync.aligned.m8n8.x4.shared.b16 {%0,%1,%2,%3}, [%4];"
        : "=r"(r[0]), "=r"(r[1]), "=r"(r[2]), "=r"(r[3]) : "r"(addr));
}
__device__ __forceinline__ void ldsm_x4_t(uint32_t* r, uint32_t addr) {
    asm volatile("ldmatrix.sync.aligned.m8n8.x4.trans.shared.b16 {%0,%1,%2,%3}, [%4];"
        : "=r"(r[0]), "=r"(r[1]), "=r"(r[2]), "=r"(r[3]) : "r"(addr));
}
__device__ __forceinline__ void mma16(float* d, const uint32_t* a,
                                      uint32_t b0, uint32_t b1) {
    asm volatile(
        "mma.sync.aligned.m16n8k16.row.col.f32.f16.f16.f32 "
        "{%0,%1,%2,%3}, {%4,%5,%6,%7}, {%8,%9}, {%0,%1,%2,%3};"
        : "+f"(d[0]), "+f"(d[1]), "+f"(d[2]), "+f"(d[3])
        : "r"(a[0]), "r"(a[1]), "r"(a[2]), "r"(a[3]), "r"(b0), "r"(b1));
}
__device__ __forceinline__ uint32_t pkh2(float lo, float hi) {
    uint32_t r;
    asm("cvt.rn.f16x2.f32 %0, %1, %2;" : "=r"(r) : "f"(hi), "f"(lo));
    return r;
}

// ---------------------------------------------------------------------------
// f32 -> half conversion
// ---------------------------------------------------------------------------
__global__ __launch_bounds__(256) void f2h_kernel(
    const float* __restrict__ in, __half* __restrict__ out, int n4)
{
    int i = blockIdx.x * blockDim.x + threadIdx.x;
    if (i < n4) {
        float4 v = ((const float4*)in)[i];
        ((uint2*)out)[i] = make_uint2(pkh2(v.x, v.y), pkh2(v.z, v.w));
    }
}

// ---------------------------------------------------------------------------
// Fused transpose of all 4 weight matrices (f32 -> half, out[c][r] = in[r][c]).
// Flattened 32x32 tile index over {Wq, Wk, Wv, Wo}; all R = 2048, ostride 2048.
// ---------------------------------------------------------------------------
__global__ __launch_bounds__(256) void transpose_all_kernel(
    const float* __restrict__ Wq, const float* __restrict__ Wk,
    const float* __restrict__ Wv, const float* __restrict__ Wo,
    __half* __restrict__ wqkvt, __half* __restrict__ wot)
{
    int t = blockIdx.x;
    const float* src; __half* dst; int C;
    if (t < 4096)      { src = Wq; dst = wqkvt;                         C = 2048; }
    else if (t < 4352) { t -= 4096; src = Wk; dst = wqkvt + (size_t)2048 * DIM_; C = 128; }
    else if (t < 4608) { t -= 4352; src = Wv; dst = wqkvt + (size_t)2176 * DIM_; C = 128; }
    else               { t -= 4608; src = Wo; dst = wot;                C = 2048; }
    const int tilesC = C / 32;
    const int c0 = (t % tilesC) * 32, r0 = (t / tilesC) * 32;

    __shared__ float tbuf[32][33];
    const int x = threadIdx.x & 31, y = (threadIdx.x >> 5) * 4;  // 32 x 8 (y step 4? no)
    // 256 threads = 32 x 8
    const int yy = threadIdx.x >> 5;  // 0..7
    #pragma unroll
    for (int i = 0; i < 32; i += 8)
        tbuf[yy + i][x] = src[(size_t)(r0 + yy + i) * C + c0 + x];
    __syncthreads();
    #pragma unroll
    for (int i = 0; i < 32; i += 8)
        dst[(size_t)(c0 + yy + i) * DIM_ + r0 + x] = __float2half_rn(tbuf[x][yy + i]);
    (void)y;
}

// ---------------------------------------------------------------------------
// fp16 mma GEMM: C[M,N] = A[M,K] * Bt[N,K]^T.  BM=BN=128, BK=32, 4-stage
// cp.async, 256 threads = 8 warps (4m x 2n), warp tile 32x64.  (R5 config)
// ---------------------------------------------------------------------------
#define G_STG_B 10240           // 128 rows * 80B
#define GEMM_SMEM (4 * 2 * G_STG_B)   // 81920 -> 2 CTAs/SM

template<bool OUT_HALF>
__global__ __launch_bounds__(256) void gemm16_kernel(
    int M, int N, int K,
    const __half* __restrict__ A, const __half* __restrict__ Bt, void* Cout)
{
    extern __shared__ char smem[];
    const uint32_t sA = smem_u32(smem);
    const uint32_t sB = sA + 4 * G_STG_B;

    const int tid = threadIdx.x, wid = tid >> 5, lane = tid & 31;
    const int grp = lane >> 2, tig = lane & 3;
    const int lrow = lane & 15, lhi = lane >> 4;
    const int wm = wid & 3, wn = wid >> 2;
    const int bm = blockIdx.y * 128, bn = blockIdx.x * 128;

    float acc[2][8][4];
    #pragma unroll
    for (int mt = 0; mt < 2; ++mt)
        #pragma unroll
        for (int nb = 0; nb < 8; ++nb)
            #pragma unroll
            for (int e = 0; e < 4; ++e) acc[mt][nb][e] = 0.f;

    const int ld_row = tid >> 1, ld_ch = (tid & 1) * 2;
    const __half* Asrc = A  + (size_t)(bm + ld_row) * K + ld_ch * 8;
    const __half* Bsrc = Bt + (size_t)(bn + ld_row) * K + ld_ch * 8;
    const uint32_t Adst = sA + ld_row * 80 + ld_ch * 16;
    const uint32_t Bdst = sB + ld_row * 80 + ld_ch * 16;

    auto issue = [&](int it, int stg) {
        const __half* as = Asrc + it * 32;
        const __half* bs = Bsrc + it * 32;
        uint32_t ad = Adst + stg * G_STG_B;
        uint32_t bd = Bdst + stg * G_STG_B;
        cp16(ad, as); cp16(ad + 16, as + 8);
        cp16(bd, bs); cp16(bd + 16, bs + 8);
    };

    const int NIT = K / 32;
    issue(0, 0); CP_COMMIT();
    issue(1, 1); CP_COMMIT();
    issue(2, 2); CP_COMMIT();

    const uint32_t offA0 = (wm * 32 + lrow) * 80 + lhi * 16;
    const uint32_t offB0 = (wn * 64 + lrow) * 80 + lhi * 16;

    for (int it = 0; it < NIT; ++it) {
        CP_WAIT(2);
        __syncthreads();
        if (it + 3 < NIT) issue(it + 3, (it + 3) & 3);
        CP_COMMIT();

        const uint32_t cA = sA + (it & 3) * G_STG_B + offA0;
        const uint32_t cB = sB + (it & 3) * G_STG_B + offB0;
        #pragma unroll
        for (int ks = 0; ks < 2; ++ks) {
            uint32_t a[2][4];
            ldsm_x4(a[0], cA + ks * 32);
            ldsm_x4(a[1], cA + 16 * 80 + ks * 32);
            #pragma unroll
            for (int j = 0; j < 4; ++j) {
                uint32_t bb[4];
                ldsm_x4(bb, cB + j * 16 * 80 + ks * 32);
                #pragma unroll
                for (int mt = 0; mt < 2; ++mt) {
                    mma16(acc[mt][2 * j],     a[mt], bb[0], bb[2]);
                    mma16(acc[mt][2 * j + 1], a[mt], bb[1], bb[3]);
                }
            }
        }
    }

    #pragma unroll
    for (int mt = 0; mt < 2; ++mt) {
        const int m = bm + wm * 32 + mt * 16 + grp;
        #pragma unroll
        for (int nb = 0; nb < 8; ++nb) {
            const int n = bn + wn * 64 + nb * 8 + 2 * tig;
            if (OUT_HALF) {
                __half* C = (__half*)Cout;
                *(uint32_t*)&C[(size_t)m * N + n] = pkh2(acc[mt][nb][0], acc[mt][nb][1]);
                *(uint32_t*)&C[(size_t)(m + 8) * N + n] = pkh2(acc[mt][nb][2], acc[mt][nb][3]);
            } else {
                float* C = (float*)Cout;
                *(float2*)&C[(size_t)m * N + n] = make_float2(acc[mt][nb][0], acc[mt][nb][1]);
                *(float2*)&C[(size_t)(m + 8) * N + n] = make_float2(acc[mt][nb][2], acc[mt][nb][3]);
            }
        }
    }
}

// ---------------------------------------------------------------------------
// Fused RoPE + RMSNorm over q AND k, in place. One warp per 128-dim vector.
// 17 vectors per token: slots 0..15 = q heads (cols 0..2047), slot 16 = k
// (cols 2048..2175). v untouched.
// ---------------------------------------------------------------------------
__global__ __launch_bounds__(256) void rope16_kernel(
    __half* __restrict__ qkv,
    const float* __restrict__ cosb, const float* __restrict__ sinb)
{
    const int vec = (blockIdx.x * blockDim.x + threadIdx.x) >> 5;
    const int lane = threadIdx.x & 31;
    const int tok = vec / 17, slot = vec - tok * 17;
    const int l = tok % L_;

    __half* p = qkv + (size_t)tok * QKV_ + (size_t)slot * 128;
    float e0 = __half2float(p[lane]);
    float e1 = __half2float(p[lane + 32]);
    float e2 = __half2float(p[lane + 64]);
    float e3 = __half2float(p[lane + 96]);
    float c0 = cosb[l * 64 + lane];
    float s0 = sinb[l * 64 + lane];
    float c1 = cosb[l * 64 + lane + 32];
    float s1 = sinb[l * 64 + lane + 32];

    float r0 =  e0 * c0 + e2 * s0;
    float r2 = -e0 * s0 + e2 * c0;
    float r1 =  e1 * c1 + e3 * s1;
    float r3 = -e1 * s1 + e3 * c1;

    float ss = r0 * r0 + r1 * r1 + r2 * r2 + r3 * r3;
    #pragma unroll
    for (int o = 16; o; o >>= 1) ss += __shfl_xor_sync(0xffffffffu, ss, o);
    float sc = rsqrtf(ss * (1.0f / 128.0f) + 1e-6f);

    p[lane]      = __float2half_rn(r0 * sc);
    p[lane + 32] = __float2half_rn(r1 * sc);
    p[lane + 64] = __float2half_rn(r2 * sc);
    p[lane + 96] = __float2half_rn(r3 * sc);
}

// ---------------------------------------------------------------------------
// fp16 flash attention (causal MQA) on fused qkv buffer (stride 2304).
// BQ=128 rows/CTA, key tiles of 64, 8 warps each owning a 16-row band.
// ---------------------------------------------------------------------------
#define FL_SMEM (128*272 + 4*64*272)    // Q + 2*(K+V)

__global__ __launch_bounds__(256) void flash16_kernel(
    const __half* __restrict__ qkv, __half* __restrict__ aoh)
{
    extern __shared__ char smem[];
    const uint32_t sQ = smem_u32(smem);
    const uint32_t sKV = sQ + 128 * 272;

    const int tid = threadIdx.x, w = tid >> 5, lane = tid & 31;
    const int grp = lane >> 2, tig = lane & 3;
    const int lrow = lane & 15, lhi = lane >> 4;
    const int qx = gridDim.x - 1 - blockIdx.x;     // heavy blocks first
    const int q0 = qx * 128, h = blockIdx.y, b = blockIdx.z;

    {
        const int row = tid >> 1, c0 = (tid & 1) * 8;
        const __half* src = qkv + (size_t)(b * L_ + q0 + row) * QKV_ + h * HD_ + c0 * 8;
        const uint32_t dst = sQ + row * 272 + c0 * 16;
        #pragma unroll
        for (int c = 0; c < 8; ++c) cp16(dst + c * 16, src + c * 8);
    }
    const int kvrow = tid >> 2, kvc = (tid & 3) * 4;
    auto issue_kv = [&](int k0, int buf) {
        const __half* base = qkv + (size_t)(b * L_ + k0 + kvrow) * QKV_ + 2048 + kvc * 8;
        const uint32_t kd = sKV + buf * (2 * 64 * 272) + kvrow * 272 + kvc * 16;
        const uint32_t vd = kd + 64 * 272;
        #pragma unroll
        for (int c = 0; c < 4; ++c) {
            cp16(kd + c * 16, base + c * 8);
            cp16(vd + c * 16, base + 128 + c * 8);
        }
    };
    issue_kv(0, 0); CP_COMMIT(); CP_WAIT(0); __syncthreads();

    float m0 = -1e30f, m1 = -1e30f, l0 = 0.f, l1 = 0.f;
    float o[16][4];
    #pragma unroll
    for (int d = 0; d < 16; ++d)
        #pragma unroll
        for (int e = 0; e < 4; ++e) o[d][e] = 0.f;

    const float sc = 0.08838834764831843f * 1.4426950408889634f;
    const int ntiles = q0 / 64 + 2;
    const int wrow = q0 + w * 16;

    for (int t = 0; t < ntiles; ++t) {
        const int k0 = t * 64;
        if (t + 1 < ntiles) { issue_kv(k0 + 64, (t + 1) & 1); CP_COMMIT(); }

        const uint32_t cK = sKV + (t & 1) * (2 * 64 * 272);
        const uint32_t cV = cK + 64 * 272;

        if (k0 <= wrow + 15) {
            float s[8][4];
            #pragma unroll
            for (int nb = 0; nb < 8; ++nb)
                #pragma unroll
                for (int e = 0; e < 4; ++e) s[nb][e] = 0.f;

            #pragma unroll
            for (int ks = 0; ks < 8; ++ks) {
                uint32_t a[4];
                ldsm_x4(a, sQ + (w * 16 + lrow) * 272 + (2 * ks + lhi) * 16);
                #pragma unroll
                for (int j = 0; j < 4; ++j) {
                    uint32_t bb[4];
                    ldsm_x4(bb, cK + (j * 16 + lrow) * 272 + (2 * ks + lhi) * 16);
                    mma16(s[2 * j],     a, bb[0], bb[2]);
                    mma16(s[2 * j + 1], a, bb[1], bb[3]);
                }
            }
            #pragma unroll
            for (int nb = 0; nb < 8; ++nb)
                #pragma unroll
                for (int e = 0; e < 4; ++e) s[nb][e] *= sc;
            if (k0 + 63 > wrow) {
                const int r0g = wrow + grp, r1g = r0g + 8;
                #pragma unroll
                for (int nb = 0; nb < 8; ++nb) {
                    const int cg = k0 + nb * 8 + 2 * tig;
                    if (cg     > r0g) s[nb][0] = -1e30f;
                    if (cg + 1 > r0g) s[nb][1] = -1e30f;
                    if (cg     > r1g) s[nb][2] = -1e30f;
                    if (cg + 1 > r1g) s[nb][3] = -1e30f;
                }
            }
            float mx0 = -1e30f, mx1 = -1e30f;
            #pragma unroll
            for (int nb = 0; nb < 8; ++nb) {
                mx0 = fmaxf(mx0, fmaxf(s[nb][0], s[nb][1]));
                mx1 = fmaxf(mx1, fmaxf(s[nb][2], s[nb][3]));
            }
            mx0 = fmaxf(mx0, __shfl_xor_sync(0xffffffffu, mx0, 1));
            mx0 = fmaxf(mx0, __shfl_xor_sync(0xffffffffu, mx0, 2));
            mx1 = fmaxf(mx1, __shfl_xor_sync(0xffffffffu, mx1, 1));
            mx1 = fmaxf(mx1, __shfl_xor_sync(0xffffffffu, mx1, 2));
            const float mn0 = fmaxf(m0, mx0), mn1 = fmaxf(m1, mx1);
            const float al0 = exp2f(m0 - mn0), al1 = exp2f(m1 - mn1);
            m0 = mn0; m1 = mn1;

            float sum0 = 0.f, sum1 = 0.f;
            #pragma unroll
            for (int nb = 0; nb < 8; ++nb) {
                s[nb][0] = exp2f(s[nb][0] - mn0); sum0 += s[nb][0];
                s[nb][1] = exp2f(s[nb][1] - mn0); sum0 += s[nb][1];
                s[nb][2] = exp2f(s[nb][2] - mn1); sum1 += s[nb][2];
                s[nb][3] = exp2f(s[nb][3] - mn1); sum1 += s[nb][3];
            }
            sum0 += __shfl_xor_sync(0xffffffffu, sum0, 1);
            sum0 += __shfl_xor_sync(0xffffffffu, sum0, 2);
            sum1 += __shfl_xor_sync(0xffffffffu, sum1, 1);
            sum1 += __shfl_xor_sync(0xffffffffu, sum1, 2);
            l0 = l0 * al0 + sum0;
            l1 = l1 * al1 + sum1;

            uint32_t pa[4][4];
            #pragma unroll
            for (int kp = 0; kp < 4; ++kp) {
                pa[kp][0] = pkh2(s[2 * kp][0],     s[2 * kp][1]);
                pa[kp][1] = pkh2(s[2 * kp][2],     s[2 * kp][3]);
                pa[kp][2] = pkh2(s[2 * kp + 1][0], s[2 * kp + 1][1]);
                pa[kp][3] = pkh2(s[2 * kp + 1][2], s[2 * kp + 1][3]);
            }
            #pragma unroll
            for (int d = 0; d < 16; ++d) {
                o[d][0] *= al0; o[d][1] *= al0;
                o[d][2] *= al1; o[d][3] *= al1;
            }
            #pragma unroll
            for (int kp = 0; kp < 4; ++kp)
                #pragma unroll
                for (int j = 0; j < 8; ++j) {
                    uint32_t vv[4];
                    ldsm_x4_t(vv, cV + (kp * 16 + lrow) * 272 + (2 * j + lhi) * 16);
                    mma16(o[2 * j],     pa[kp], vv[0], vv[1]);
                    mma16(o[2 * j + 1], pa[kp], vv[2], vv[3]);
                }
        }
        if (t + 1 < ntiles) { CP_WAIT(0); __syncthreads(); }
    }

    const float inv0 = 1.f / l0, inv1 = 1.f / l1;
    const int r0g = q0 + w * 16 + grp;
    __half* op0 = aoh + (size_t)(b * L_ + r0g) * DIM_ + h * HD_;
    __half* op1 = op0 + (size_t)8 * DIM_;
    #pragma unroll
    for (int d = 0; d < 16; ++d) {
        const int col = d * 8 + 2 * tig;
        *(uint32_t*)(op0 + col) = pkh2(o[d][0] * inv0, o[d][1] * inv0);
        *(uint32_t*)(op1 + col) = pkh2(o[d][2] * inv1, o[d][3] * inv1);
    }
}

// ---------------------------------------------------------------------------
extern "C" void kernel_launch(void* const* d_in, const int* in_sizes, int n_in,
                              void* d_out, int out_size)
{
    const float* x    = (const float*)d_in[0];
    const float* cosb = (const float*)d_in[1];
    const float* sinb = (const float*)d_in[2];
    const float* Wq   = (const float*)d_in[3];
    const float* Wk   = (const float*)d_in[4];
    const float* Wv   = (const float*)d_in[5];
    const float* Wo   = (const float*)d_in[6];
    float* out = (float*)d_out;

    __half *xh, *wqkvt, *wot, *qkv, *aoh;
    cudaGetSymbolAddress((void**)&xh,    g_xh);
    cudaGetSymbolAddress((void**)&wqkvt, g_wqkvt);
    cudaGetSymbolAddress((void**)&wot,   g_wot);
    cudaGetSymbolAddress((void**)&qkv,   g_qkv);
    cudaGetSymbolAddress((void**)&aoh,   g_aoh);

    const int M = B_ * L_;   // 4096

    cudaFuncSetAttribute(gemm16_kernel<true>,
                         cudaFuncAttributeMaxDynamicSharedMemorySize, GEMM_SMEM);
    cudaFuncSetAttribute(gemm16_kernel<false>,
                         cudaFuncAttributeMaxDynamicSharedMemorySize, GEMM_SMEM);
    cudaFuncSetAttribute(flash16_kernel,
                         cudaFuncAttributeMaxDynamicSharedMemorySize, FL_SMEM);

    // 0) convert x to half; transpose all weights in one launch
    f2h_kernel<<<(M * DIM_ / 4 + 255) / 256, 256>>>(x, xh, M * DIM_ / 4);
    transpose_all_kernel<<<8704, 256>>>(Wq, Wk, Wv, Wo, wqkvt, wot);

    // 1) fused QKV projection: (4096, 2304) = xh @ wqkvt^T  (R5 tile config)
    gemm16_kernel<true><<<dim3(QKV_/128, M/128), 256, GEMM_SMEM>>>(M, QKV_, DIM_, xh, wqkvt, qkv);

    // 2) RoPE + RMSNorm in place, q + k fused (17 vecs/token)
    rope16_kernel<<<M * 17 * 32 / 256, 256>>>(qkv, cosb, sinb);

    // 3) fp16 flash attention
    flash16_kernel<<<dim3(L_/128, H_, B_), 256, FL_SMEM>>>(qkv, aoh);

    // 4) output projection (float out)
    gemm16_kernel<false><<<dim3(DIM_/128, M/128), 256, GEMM_SMEM>>>(M, DIM_, DIM_, aoh, wot, out);
}

// round 8
// speedup vs baseline: 1.1253x; 1.0048x over previous
#include <cuda_runtime.h>
#include <cuda_fp16.h>
#include <cstdint>
#include <math.h>

#define B_  2
#define L_  2048
#define DIM_ 2048
#define H_  16
#define HD_ 128
#define QKV_ 2304   // 2048 q + 128 k + 128 v

// ---------------------------------------------------------------------------
// Scratch (device globals)
// ---------------------------------------------------------------------------
__device__ __half g_xh   [(size_t)B_ * L_ * DIM_];   // x in half
__device__ __half g_wqkvt[(size_t)QKV_ * DIM_];      // [Wq^T;Wk^T;Wv^T] half [2304][2048]
__device__ __half g_wot  [(size_t)DIM_ * DIM_];      // Wo^T half
__device__ __half g_qkv  [(size_t)B_ * L_ * QKV_];   // fused q|k|v proj (roped in place)
__device__ __half g_aoh  [(size_t)B_ * L_ * DIM_];   // attention out half

// ---------------------------------------------------------------------------
// PTX helpers
// ---------------------------------------------------------------------------
__device__ __forceinline__ uint32_t smem_u32(const void* p) {
    uint32_t a;
    asm("{ .reg .u64 t; cvta.to.shared.u64 t, %1; cvt.u32.u64 %0, t; }"
        : "=r"(a) : "l"(p));
    return a;
}
__device__ __forceinline__ void cp16(uint32_t dst, const void* src) {
    asm volatile("cp.async.cg.shared.global [%0], [%1], 16;" :: "r"(dst), "l"(src));
}
#define CP_COMMIT() asm volatile("cp.async.commit_group;")
#define CP_WAIT(n)  asm volatile("cp.async.wait_group %0;" :: "n"(n))

__device__ __forceinline__ void ldsm_x4(uint32_t* r, uint32_t addr) {
    asm volatile("ldmatrix.sync.aligned.m8n8.x4.shared.b16 {%0,%1,%2,%3}, [%4];"
        : "=r"(r[0]), "=r"(r[1]), "=r"(r[2]), "=r"(r[3]) : "r"(addr));
}
__device__ __forceinline__ void ldsm_x4_t(uint32_t* r, uint32_t addr) {
    asm volatile("ldmatrix.sync.aligned.m8n8.x4.trans.shared.b16 {%0,%1,%2,%3}, [%4];"
        : "=r"(r[0]), "=r"(r[1]), "=r"(r[2]), "=r"(r[3]) : "r"(addr));
}
__device__ __forceinline__ void mma16(float* d, const uint32_t* a,
                                      uint32_t b0, uint32_t b1) {
    asm volatile(
        "mma.sync.aligned.m16n8k16.row.col.f32.f16.f16.f32 "
        "{%0,%1,%2,%3}, {%4,%5,%6,%7}, {%8,%9}, {%0,%1,%2,%3};"
        : "+f"(d[0]), "+f"(d[1]), "+f"(d[2]), "+f"(d[3])
        : "r"(a[0]), "r"(a[1]), "r"(a[2]), "r"(a[3]), "r"(b0), "r"(b1));
}
__device__ __forceinline__ uint32_t pkh2(float lo, float hi) {
    uint32_t r;
    asm("cvt.rn.f16x2.f32 %0, %1, %2;" : "=r"(r) : "f"(hi), "f"(lo));
    return r;
}

// ---------------------------------------------------------------------------
// prep: f2h of x (blocks 0..8191) + all 4 weight transposes (blocks 8192..16895)
// ---------------------------------------------------------------------------
__global__ __launch_bounds__(256) void prep_kernel(
    const float* __restrict__ x,
    const float* __restrict__ Wq, const float* __restrict__ Wk,
    const float* __restrict__ Wv, const float* __restrict__ Wo,
    __half* __restrict__ xh, __half* __restrict__ wqkvt, __half* __restrict__ wot)
{
    if (blockIdx.x < 8192) {
        const int i = blockIdx.x * 256 + threadIdx.x;   // over 2M float4
        float4 v = ((const float4*)x)[i];
        ((uint2*)xh)[i] = make_uint2(pkh2(v.x, v.y), pkh2(v.z, v.w));
        return;
    }
    int t = blockIdx.x - 8192;
    const float* src; __half* dst; int C;
    if (t < 4096)      { src = Wq; dst = wqkvt;                              C = 2048; }
    else if (t < 4352) { t -= 4096; src = Wk; dst = wqkvt + (size_t)2048 * DIM_; C = 128; }
    else if (t < 4608) { t -= 4352; src = Wv; dst = wqkvt + (size_t)2176 * DIM_; C = 128; }
    else               { t -= 4608; src = Wo; dst = wot;                     C = 2048; }
    const int tilesC = C / 32;
    const int c0 = (t % tilesC) * 32, r0 = (t / tilesC) * 32;

    __shared__ float tbuf[32][33];
    const int xx = threadIdx.x & 31;
    const int yy = threadIdx.x >> 5;  // 0..7
    #pragma unroll
    for (int i = 0; i < 32; i += 8)
        tbuf[yy + i][xx] = src[(size_t)(r0 + yy + i) * C + c0 + xx];
    __syncthreads();
    #pragma unroll
    for (int i = 0; i < 32; i += 8)
        dst[(size_t)(c0 + yy + i) * DIM_ + r0 + xx] = __float2half_rn(tbuf[xx][yy + i]);
}

// ---------------------------------------------------------------------------
// fp16 mma GEMM: C[M,N] = A[M,K] * Bt[N,K]^T.  BM=BN=128, BK=32, 4-stage
// cp.async, 256 threads = 8 warps (4m x 2n), warp tile 32x64.  (R5 config)
// ---------------------------------------------------------------------------
#define G_STG_B 10240           // 128 rows * 80B
#define GEMM_SMEM (4 * 2 * G_STG_B)   // 81920 -> 2 CTAs/SM

template<bool OUT_HALF>
__global__ __launch_bounds__(256) void gemm16_kernel(
    int M, int N, int K,
    const __half* __restrict__ A, const __half* __restrict__ Bt, void* Cout)
{
    extern __shared__ char smem[];
    const uint32_t sA = smem_u32(smem);
    const uint32_t sB = sA + 4 * G_STG_B;

    const int tid = threadIdx.x, wid = tid >> 5, lane = tid & 31;
    const int grp = lane >> 2, tig = lane & 3;
    const int lrow = lane & 15, lhi = lane >> 4;
    const int wm = wid & 3, wn = wid >> 2;
    const int bm = blockIdx.y * 128, bn = blockIdx.x * 128;

    float acc[2][8][4];
    #pragma unroll
    for (int mt = 0; mt < 2; ++mt)
        #pragma unroll
        for (int nb = 0; nb < 8; ++nb)
            #pragma unroll
            for (int e = 0; e < 4; ++e) acc[mt][nb][e] = 0.f;

    const int ld_row = tid >> 1, ld_ch = (tid & 1) * 2;
    const __half* Asrc = A  + (size_t)(bm + ld_row) * K + ld_ch * 8;
    const __half* Bsrc = Bt + (size_t)(bn + ld_row) * K + ld_ch * 8;
    const uint32_t Adst = sA + ld_row * 80 + ld_ch * 16;
    const uint32_t Bdst = sB + ld_row * 80 + ld_ch * 16;

    auto issue = [&](int it, int stg) {
        const __half* as = Asrc + it * 32;
        const __half* bs = Bsrc + it * 32;
        uint32_t ad = Adst + stg * G_STG_B;
        uint32_t bd = Bdst + stg * G_STG_B;
        cp16(ad, as); cp16(ad + 16, as + 8);
        cp16(bd, bs); cp16(bd + 16, bs + 8);
    };

    const int NIT = K / 32;
    issue(0, 0); CP_COMMIT();
    issue(1, 1); CP_COMMIT();
    issue(2, 2); CP_COMMIT();

    const uint32_t offA0 = (wm * 32 + lrow) * 80 + lhi * 16;
    const uint32_t offB0 = (wn * 64 + lrow) * 80 + lhi * 16;

    for (int it = 0; it < NIT; ++it) {
        CP_WAIT(2);
        __syncthreads();
        if (it + 3 < NIT) issue(it + 3, (it + 3) & 3);
        CP_COMMIT();

        const uint32_t cA = sA + (it & 3) * G_STG_B + offA0;
        const uint32_t cB = sB + (it & 3) * G_STG_B + offB0;
        #pragma unroll
        for (int ks = 0; ks < 2; ++ks) {
            uint32_t a[2][4];
            ldsm_x4(a[0], cA + ks * 32);
            ldsm_x4(a[1], cA + 16 * 80 + ks * 32);
            #pragma unroll
            for (int j = 0; j < 4; ++j) {
                uint32_t bb[4];
                ldsm_x4(bb, cB + j * 16 * 80 + ks * 32);
                #pragma unroll
                for (int mt = 0; mt < 2; ++mt) {
                    mma16(acc[mt][2 * j],     a[mt], bb[0], bb[2]);
                    mma16(acc[mt][2 * j + 1], a[mt], bb[1], bb[3]);
                }
            }
        }
    }

    #pragma unroll
    for (int mt = 0; mt < 2; ++mt) {
        const int m = bm + wm * 32 + mt * 16 + grp;
        #pragma unroll
        for (int nb = 0; nb < 8; ++nb) {
            const int n = bn + wn * 64 + nb * 8 + 2 * tig;
            if (OUT_HALF) {
                __half* C = (__half*)Cout;
                *(uint32_t*)&C[(size_t)m * N + n] = pkh2(acc[mt][nb][0], acc[mt][nb][1]);
                *(uint32_t*)&C[(size_t)(m + 8) * N + n] = pkh2(acc[mt][nb][2], acc[mt][nb][3]);
            } else {
                float* C = (float*)Cout;
                *(float2*)&C[(size_t)m * N + n] = make_float2(acc[mt][nb][0], acc[mt][nb][1]);
                *(float2*)&C[(size_t)(m + 8) * N + n] = make_float2(acc[mt][nb][2], acc[mt][nb][3]);
            }
        }
    }
}

// ---------------------------------------------------------------------------
// Fused RoPE + RMSNorm over q AND k, in place, coalesced half2 path.
// One warp per 128-dim vector; 17 vectors/token (16 q heads + k).
// Lane owns column pairs (2l, 2l+1) and (64+2l, 64+2l+1).
// ---------------------------------------------------------------------------
__global__ __launch_bounds__(256) void rope16_kernel(
    __half* __restrict__ qkv,
    const float* __restrict__ cosb, const float* __restrict__ sinb)
{
    const int vec = (blockIdx.x * blockDim.x + threadIdx.x) >> 5;
    const int lane = threadIdx.x & 31;
    const int tok = vec / 17, slot = vec - tok * 17;
    const int l = tok % L_;

    __half2* p2 = (__half2*)(qkv + (size_t)tok * QKV_ + (size_t)slot * 128);
    float2 x1 = __half22float2(p2[lane]);        // cols 2l, 2l+1
    float2 x2 = __half22float2(p2[lane + 32]);   // cols 64+2l, 64+2l+1
    float2 c  = *(const float2*)&cosb[l * 64 + 2 * lane];
    float2 s  = *(const float2*)&sinb[l * 64 + 2 * lane];

    float r1x =  x1.x * c.x + x2.x * s.x;        // out col 2l
    float r1y =  x1.y * c.y + x2.y * s.y;        // out col 2l+1
    float r2x = -x1.x * s.x + x2.x * c.x;        // out col 64+2l
    float r2y = -x1.y * s.y + x2.y * c.y;

    float ss = r1x * r1x + r1y * r1y + r2x * r2x + r2y * r2y;
    #pragma unroll
    for (int o = 16; o; o >>= 1) ss += __shfl_xor_sync(0xffffffffu, ss, o);
    float sc = rsqrtf(ss * (1.0f / 128.0f) + 1e-6f);

    p2[lane]      = __float22half2_rn(make_float2(r1x * sc, r1y * sc));
    p2[lane + 32] = __float22half2_rn(make_float2(r2x * sc, r2y * sc));
}

// ---------------------------------------------------------------------------
// fp16 flash attention (causal MQA) on fused qkv buffer (stride 2304).
// BQ=128 rows/CTA, key tiles of 64, 8 warps each owning a 16-row band.
// ---------------------------------------------------------------------------
#define FL_SMEM (128*272 + 4*64*272)    // Q + 2*(K+V)

__global__ __launch_bounds__(256) void flash16_kernel(
    const __half* __restrict__ qkv, __half* __restrict__ aoh)
{
    extern __shared__ char smem[];
    const uint32_t sQ = smem_u32(smem);
    const uint32_t sKV = sQ + 128 * 272;

    const int tid = threadIdx.x, w = tid >> 5, lane = tid & 31;
    const int grp = lane >> 2, tig = lane & 3;
    const int lrow = lane & 15, lhi = lane >> 4;
    const int qx = gridDim.x - 1 - blockIdx.x;     // heavy blocks first
    const int q0 = qx * 128, h = blockIdx.y, b = blockIdx.z;

    {
        const int row = tid >> 1, c0 = (tid & 1) * 8;
        const __half* src = qkv + (size_t)(b * L_ + q0 + row) * QKV_ + h * HD_ + c0 * 8;
        const uint32_t dst = sQ + row * 272 + c0 * 16;
        #pragma unroll
        for (int c = 0; c < 8; ++c) cp16(dst + c * 16, src + c * 8);
    }
    const int kvrow = tid >> 2, kvc = (tid & 3) * 4;
    auto issue_kv = [&](int k0, int buf) {
        const __half* base = qkv + (size_t)(b * L_ + k0 + kvrow) * QKV_ + 2048 + kvc * 8;
        const uint32_t kd = sKV + buf * (2 * 64 * 272) + kvrow * 272 + kvc * 16;
        const uint32_t vd = kd + 64 * 272;
        #pragma unroll
        for (int c = 0; c < 4; ++c) {
            cp16(kd + c * 16, base + c * 8);
            cp16(vd + c * 16, base + 128 + c * 8);
        }
    };
    issue_kv(0, 0); CP_COMMIT(); CP_WAIT(0); __syncthreads();

    float m0 = -1e30f, m1 = -1e30f, l0 = 0.f, l1 = 0.f;
    float o[16][4];
    #pragma unroll
    for (int d = 0; d < 16; ++d)
        #pragma unroll
        for (int e = 0; e < 4; ++e) o[d][e] = 0.f;

    const float sc = 0.08838834764831843f * 1.4426950408889634f;
    const int ntiles = q0 / 64 + 2;
    const int wrow = q0 + w * 16;

    for (int t = 0; t < ntiles; ++t) {
        const int k0 = t * 64;
        if (t + 1 < ntiles) { issue_kv(k0 + 64, (t + 1) & 1); CP_COMMIT(); }

        const uint32_t cK = sKV + (t & 1) * (2 * 64 * 272);
        const uint32_t cV = cK + 64 * 272;

        if (k0 <= wrow + 15) {
            float s[8][4];
            #pragma unroll
            for (int nb = 0; nb < 8; ++nb)
                #pragma unroll
                for (int e = 0; e < 4; ++e) s[nb][e] = 0.f;

            #pragma unroll
            for (int ks = 0; ks < 8; ++ks) {
                uint32_t a[4];
                ldsm_x4(a, sQ + (w * 16 + lrow) * 272 + (2 * ks + lhi) * 16);
                #pragma unroll
                for (int j = 0; j < 4; ++j) {
                    uint32_t bb[4];
                    ldsm_x4(bb, cK + (j * 16 + lrow) * 272 + (2 * ks + lhi) * 16);
                    mma16(s[2 * j],     a, bb[0], bb[2]);
                    mma16(s[2 * j + 1], a, bb[1], bb[3]);
                }
            }
            #pragma unroll
            for (int nb = 0; nb < 8; ++nb)
                #pragma unroll
                for (int e = 0; e < 4; ++e) s[nb][e] *= sc;
            if (k0 + 63 > wrow) {
                const int r0g = wrow + grp, r1g = r0g + 8;
                #pragma unroll
                for (int nb = 0; nb < 8; ++nb) {
                    const int cg = k0 + nb * 8 + 2 * tig;
                    if (cg     > r0g) s[nb][0] = -1e30f;
                    if (cg + 1 > r0g) s[nb][1] = -1e30f;
                    if (cg     > r1g) s[nb][2] = -1e30f;
                    if (cg + 1 > r1g) s[nb][3] = -1e30f;
                }
            }
            float mx0 = -1e30f, mx1 = -1e30f;
            #pragma unroll
            for (int nb = 0; nb < 8; ++nb) {
                mx0 = fmaxf(mx0, fmaxf(s[nb][0], s[nb][1]));
                mx1 = fmaxf(mx1, fmaxf(s[nb][2], s[nb][3]));
            }
            mx0 = fmaxf(mx0, __shfl_xor_sync(0xffffffffu, mx0, 1));
            mx0 = fmaxf(mx0, __shfl_xor_sync(0xffffffffu, mx0, 2));
            mx1 = fmaxf(mx1, __shfl_xor_sync(0xffffffffu, mx1, 1));
            mx1 = fmaxf(mx1, __shfl_xor_sync(0xffffffffu, mx1, 2));
            const float mn0 = fmaxf(m0, mx0), mn1 = fmaxf(m1, mx1);
            const float al0 = exp2f(m0 - mn0), al1 = exp2f(m1 - mn1);
            m0 = mn0; m1 = mn1;

            float sum0 = 0.f, sum1 = 0.f;
            #pragma unroll
            for (int nb = 0; nb < 8; ++nb) {
                s[nb][0] = exp2f(s[nb][0] - mn0); sum0 += s[nb][0];
                s[nb][1] = exp2f(s[nb][1] - mn0); sum0 += s[nb][1];
                s[nb][2] = exp2f(s[nb][2] - mn1); sum1 += s[nb][2];
                s[nb][3] = exp2f(s[nb][3] - mn1); sum1 += s[nb][3];
            }
            sum0 += __shfl_xor_sync(0xffffffffu, sum0, 1);
            sum0 += __shfl_xor_sync(0xffffffffu, sum0, 2);
            sum1 += __shfl_xor_sync(0xffffffffu, sum1, 1);
            sum1 += __shfl_xor_sync(0xffffffffu, sum1, 2);
            l0 = l0 * al0 + sum0;
            l1 = l1 * al1 + sum1;

            uint32_t pa[4][4];
            #pragma unroll
            for (int kp = 0; kp < 4; ++kp) {
                pa[kp][0] = pkh2(s[2 * kp][0],     s[2 * kp][1]);
                pa[kp][1] = pkh2(s[2 * kp][2],     s[2 * kp][3]);
                pa[kp][2] = pkh2(s[2 * kp + 1][0], s[2 * kp + 1][1]);
                pa[kp][3] = pkh2(s[2 * kp + 1][2], s[2 * kp + 1][3]);
            }
            #pragma unroll
            for (int d = 0; d < 16; ++d) {
                o[d][0] *= al0; o[d][1] *= al0;
                o[d][2] *= al1; o[d][3] *= al1;
            }
            #pragma unroll
            for (int kp = 0; kp < 4; ++kp)
                #pragma unroll
                for (int j = 0; j < 8; ++j) {
                    uint32_t vv[4];
                    ldsm_x4_t(vv, cV + (kp * 16 + lrow) * 272 + (2 * j + lhi) * 16);
                    mma16(o[2 * j],     pa[kp], vv[0], vv[1]);
                    mma16(o[2 * j + 1], pa[kp], vv[2], vv[3]);
                }
        }
        if (t + 1 < ntiles) { CP_WAIT(0); __syncthreads(); }
    }

    const float inv0 = 1.f / l0, inv1 = 1.f / l1;
    const int r0g = q0 + w * 16 + grp;
    __half* op0 = aoh + (size_t)(b * L_ + r0g) * DIM_ + h * HD_;
    __half* op1 = op0 + (size_t)8 * DIM_;
    #pragma unroll
    for (int d = 0; d < 16; ++d) {
        const int col = d * 8 + 2 * tig;
        *(uint32_t*)(op0 + col) = pkh2(o[d][0] * inv0, o[d][1] * inv0);
        *(uint32_t*)(op1 + col) = pkh2(o[d][2] * inv1, o[d][3] * inv1);
    }
}

// ---------------------------------------------------------------------------
extern "C" void kernel_launch(void* const* d_in, const int* in_sizes, int n_in,
                              void* d_out, int out_size)
{
    const float* x    = (const float*)d_in[0];
    const float* cosb = (const float*)d_in[1];
    const float* sinb = (const float*)d_in[2];
    const float* Wq   = (const float*)d_in[3];
    const float* Wk   = (const float*)d_in[4];
    const float* Wv   = (const float*)d_in[5];
    const float* Wo   = (const float*)d_in[6];
    float* out = (float*)d_out;

    __half *xh, *wqkvt, *wot, *qkv, *aoh;
    cudaGetSymbolAddress((void**)&xh,    g_xh);
    cudaGetSymbolAddress((void**)&wqkvt, g_wqkvt);
    cudaGetSymbolAddress((void**)&wot,   g_wot);
    cudaGetSymbolAddress((void**)&qkv,   g_qkv);
    cudaGetSymbolAddress((void**)&aoh,   g_aoh);

    const int M = B_ * L_;   // 4096

    cudaFuncSetAttribute(gemm16_kernel<true>,
                         cudaFuncAttributeMaxDynamicSharedMemorySize, GEMM_SMEM);
    cudaFuncSetAttribute(gemm16_kernel<false>,
                         cudaFuncAttributeMaxDynamicSharedMemorySize, GEMM_SMEM);
    cudaFuncSetAttribute(flash16_kernel,
                         cudaFuncAttributeMaxDynamicSharedMemorySize, FL_SMEM);

    // 0) prep: x -> half, weights -> transposed half (single launch)
    prep_kernel<<<16896, 256>>>(x, Wq, Wk, Wv, Wo, xh, wqkvt, wot);

    // 1) fused QKV projection
    gemm16_kernel<true><<<dim3(QKV_/128, M/128), 256, GEMM_SMEM>>>(M, QKV_, DIM_, xh, wqkvt, qkv);

    // 2) RoPE + RMSNorm in place, q + k fused (17 vecs/token), coalesced
    rope16_kernel<<<M * 17 * 32 / 256, 256>>>(qkv, cosb, sinb);

    // 3) fp16 flash attention
    flash16_kernel<<<dim3(L_/128, H_, B_), 256, FL_SMEM>>>(qkv, aoh);

    // 4) output projection (float out)
    gemm16_kernel<false><<<dim3(DIM_/128, M/128), 256, GEMM_SMEM>>>(M, DIM_, DIM_, aoh, wot, out);
}